// round 2
// baseline (speedup 1.0000x reference)
#include <cuda_runtime.h>
#include <math.h>

#define BATCH 4
#define SEQ   2048
#define HID   2048

// 64 MB scratch for scores/weights [B, Sq, Sk] (static: no allocations allowed)
static __device__ float g_scores[(size_t)BATCH * SEQ * SEQ];

#define BM 128
#define BN 128
#define BK 16
#define TM 8
#define TN 8
#define THREADS 256
#define PAD 4

// -------------------------------------------------------------------------
// Kernel 1: scores = (Q @ K^T) * scale * sigmoid(span[k])   (NT GEMM)
// -------------------------------------------------------------------------
__global__ __launch_bounds__(THREADS) void kscores(
    const float* __restrict__ Q, const float* __restrict__ K,
    const float* __restrict__ span)
{
    __shared__ float As[BK][BM + PAD];
    __shared__ float Bs[BK][BN + PAD];

    const int b  = blockIdx.z;
    const int m0 = blockIdx.y * BM;
    const int n0 = blockIdx.x * BN;
    const float* Ab = Q + (size_t)b * SEQ * HID;
    const float* Bb = K + (size_t)b * SEQ * HID;
    float*       Cb = g_scores + (size_t)b * SEQ * SEQ;

    const int tid = threadIdx.x;
    const int tx  = tid & 15;   // 0..15 -> n microtile
    const int ty  = tid >> 4;   // 0..15 -> m microtile

    float acc[TM][TN];
    #pragma unroll
    for (int i = 0; i < TM; i++)
        #pragma unroll
        for (int j = 0; j < TN; j++) acc[i][j] = 0.f;

    for (int k0 = 0; k0 < HID; k0 += BK) {
        // A tile: 128 rows x 16 cols, stored transposed As[k][m]
        #pragma unroll
        for (int l = 0; l < 2; l++) {
            int f4  = tid + l * THREADS;       // 0..511
            int row = f4 >> 2;                 // 0..127
            int kq  = (f4 & 3) * 4;            // 0,4,8,12
            float4 v = *reinterpret_cast<const float4*>(
                &Ab[(size_t)(m0 + row) * HID + k0 + kq]);
            As[kq + 0][row] = v.x;
            As[kq + 1][row] = v.y;
            As[kq + 2][row] = v.z;
            As[kq + 3][row] = v.w;
        }
        // B tile (K matrix, rows = key index, cols = d): transposed Bs[k][n]
        #pragma unroll
        for (int l = 0; l < 2; l++) {
            int f4  = tid + l * THREADS;
            int row = f4 >> 2;
            int kq  = (f4 & 3) * 4;
            float4 v = *reinterpret_cast<const float4*>(
                &Bb[(size_t)(n0 + row) * HID + k0 + kq]);
            Bs[kq + 0][row] = v.x;
            Bs[kq + 1][row] = v.y;
            Bs[kq + 2][row] = v.z;
            Bs[kq + 3][row] = v.w;
        }
        __syncthreads();

        #pragma unroll
        for (int kk = 0; kk < BK; kk++) {
            float a[TM], bb[TN];
            #pragma unroll
            for (int i = 0; i < TM; i++) a[i]  = As[kk][ty * TM + i];
            #pragma unroll
            for (int j = 0; j < TN; j++) bb[j] = Bs[kk][tx * TN + j];
            #pragma unroll
            for (int i = 0; i < TM; i++)
                #pragma unroll
                for (int j = 0; j < TN; j++)
                    acc[i][j] = fmaf(a[i], bb[j], acc[i][j]);
        }
        __syncthreads();
    }

    const float scale = 0.02209708691207961f;  // 1/sqrt(2048)
    float gate[TN];
    #pragma unroll
    for (int j = 0; j < TN; j++) {
        float s = span[n0 + tx * TN + j];
        gate[j] = scale / (1.f + __expf(-s));
    }
    #pragma unroll
    for (int i = 0; i < TM; i++) {
        int m = m0 + ty * TM + i;
        #pragma unroll
        for (int j = 0; j < TN; j += 4) {
            float4 v;
            v.x = acc[i][j + 0] * gate[j + 0];
            v.y = acc[i][j + 1] * gate[j + 1];
            v.z = acc[i][j + 2] * gate[j + 2];
            v.w = acc[i][j + 3] * gate[j + 3];
            *reinterpret_cast<float4*>(&Cb[(size_t)m * SEQ + n0 + tx * TN + j]) = v;
        }
    }
}

// -------------------------------------------------------------------------
// Kernel 2: in-place row softmax over the key axis (row length SEQ=2048)
// -------------------------------------------------------------------------
__global__ __launch_bounds__(256) void ksoftmax()
{
    const int row = blockIdx.x;             // 0 .. BATCH*SEQ-1
    float* p = g_scores + (size_t)row * SEQ;
    const int tid  = threadIdx.x;
    const int lane = tid & 31;
    const int warp = tid >> 5;

    __shared__ float red[8];

    float v[8];
    float m = -1e30f;
    #pragma unroll
    for (int i = 0; i < 8; i++) {
        v[i] = p[tid + i * 256];
        m = fmaxf(m, v[i]);
    }
    #pragma unroll
    for (int off = 16; off > 0; off >>= 1)
        m = fmaxf(m, __shfl_xor_sync(0xffffffffu, m, off));
    if (lane == 0) red[warp] = m;
    __syncthreads();
    float mall = red[0];
    #pragma unroll
    for (int w = 1; w < 8; w++) mall = fmaxf(mall, red[w]);
    __syncthreads();

    float s = 0.f;
    #pragma unroll
    for (int i = 0; i < 8; i++) {
        v[i] = __expf(v[i] - mall);
        s += v[i];
    }
    #pragma unroll
    for (int off = 16; off > 0; off >>= 1)
        s += __shfl_xor_sync(0xffffffffu, s, off);
    if (lane == 0) red[warp] = s;
    __syncthreads();
    float tot = 0.f;
    #pragma unroll
    for (int w = 0; w < 8; w++) tot += red[w];
    float inv = 1.f / tot;

    #pragma unroll
    for (int i = 0; i < 8; i++)
        p[tid + i * 256] = v[i] * inv;
}

// -------------------------------------------------------------------------
// Kernel 3: O = P @ V   (NN GEMM)
// -------------------------------------------------------------------------
__global__ __launch_bounds__(THREADS) void kout(
    const float* __restrict__ V, float* __restrict__ O)
{
    __shared__ float As[BK][BM + PAD];
    __shared__ float Bs[BK][BN + PAD];

    const int b  = blockIdx.z;
    const int m0 = blockIdx.y * BM;
    const int n0 = blockIdx.x * BN;
    const float* Ab = g_scores + (size_t)b * SEQ * SEQ;
    const float* Bb = V + (size_t)b * SEQ * HID;
    float*       Cb = O + (size_t)b * SEQ * HID;

    const int tid = threadIdx.x;
    const int tx  = tid & 15;
    const int ty  = tid >> 4;

    float acc[TM][TN];
    #pragma unroll
    for (int i = 0; i < TM; i++)
        #pragma unroll
        for (int j = 0; j < TN; j++) acc[i][j] = 0.f;

    for (int k0 = 0; k0 < SEQ; k0 += BK) {
        // A tile (P): 128 x 16, transposed As[k][m]
        #pragma unroll
        for (int l = 0; l < 2; l++) {
            int f4  = tid + l * THREADS;
            int row = f4 >> 2;
            int kq  = (f4 & 3) * 4;
            float4 v = *reinterpret_cast<const float4*>(
                &Ab[(size_t)(m0 + row) * SEQ + k0 + kq]);
            As[kq + 0][row] = v.x;
            As[kq + 1][row] = v.y;
            As[kq + 2][row] = v.z;
            As[kq + 3][row] = v.w;
        }
        // B tile (V): 16 rows x 128 cols, natural layout Bs[k][n]
        #pragma unroll
        for (int l = 0; l < 2; l++) {
            int f4  = tid + l * THREADS;       // 0..511
            int row = f4 >> 5;                 // 0..15
            int col = (f4 & 31) * 4;           // 0..124
            float4 v = *reinterpret_cast<const float4*>(
                &Bb[(size_t)(k0 + row) * HID + n0 + col]);
            *reinterpret_cast<float4*>(&Bs[row][col]) = v;
        }
        __syncthreads();

        #pragma unroll
        for (int kk = 0; kk < BK; kk++) {
            float a[TM], bb[TN];
            #pragma unroll
            for (int i = 0; i < TM; i++) a[i]  = As[kk][ty * TM + i];
            #pragma unroll
            for (int j = 0; j < TN; j++) bb[j] = Bs[kk][tx * TN + j];
            #pragma unroll
            for (int i = 0; i < TM; i++)
                #pragma unroll
                for (int j = 0; j < TN; j++)
                    acc[i][j] = fmaf(a[i], bb[j], acc[i][j]);
        }
        __syncthreads();
    }

    #pragma unroll
    for (int i = 0; i < TM; i++) {
        int m = m0 + ty * TM + i;
        #pragma unroll
        for (int j = 0; j < TN; j += 4) {
            float4 v;
            v.x = acc[i][j + 0];
            v.y = acc[i][j + 1];
            v.z = acc[i][j + 2];
            v.w = acc[i][j + 3];
            *reinterpret_cast<float4*>(&Cb[(size_t)m * HID + n0 + tx * TN + j]) = v;
        }
    }
}

// -------------------------------------------------------------------------
extern "C" void kernel_launch(void* const* d_in, const int* in_sizes, int n_in,
                              void* d_out, int out_size)
{
    const float* Q    = (const float*)d_in[0];
    const float* K    = (const float*)d_in[1];
    const float* V    = (const float*)d_in[2];
    const float* span = (const float*)d_in[3];
    float* O = (float*)d_out;

    dim3 block(THREADS);
    dim3 gridG(SEQ / BN, SEQ / BM, BATCH);

    kscores<<<gridG, block>>>(Q, K, span);
    ksoftmax<<<BATCH * SEQ, 256>>>();
    kout<<<gridG, block>>>(V, O);
}

// round 4
// speedup vs baseline: 2.5732x; 2.5732x over previous
#include <cuda_runtime.h>
#include <cuda_fp16.h>
#include <cstdint>
#include <math.h>

#define BATCH 4
#define SEQ   2048
#define HID   2048

// ---------------- static device scratch (no allocations allowed) ----------------
static __device__ float  g_scores[(size_t)BATCH * SEQ * SEQ];   // 64 MB
static __device__ __half g_Qh[(size_t)BATCH * SEQ * HID];
static __device__ __half g_Ql[(size_t)BATCH * SEQ * HID];
static __device__ __half g_Kh[(size_t)BATCH * SEQ * HID];
static __device__ __half g_Kl[(size_t)BATCH * SEQ * HID];
static __device__ __half g_Vh[(size_t)BATCH * HID * SEQ];       // transposed [b][n][k]
static __device__ __half g_Vl[(size_t)BATCH * HID * SEQ];
static __device__ __half g_Ph[(size_t)BATCH * SEQ * SEQ];
static __device__ __half g_Pl[(size_t)BATCH * SEQ * SEQ];

// ---------------- helpers ----------------
__device__ __forceinline__ uint32_t smem_to_u32(const void* p) {
    uint32_t a;
    asm("{ .reg .u64 t; cvta.to.shared.u64 t, %1; cvt.u32.u64 %0, t; }" : "=r"(a) : "l"(p));
    return a;
}

#define LDSM_X4(r0, r1, r2, r3, addr) \
    asm volatile("ldmatrix.sync.aligned.m8n8.x4.shared.b16 {%0,%1,%2,%3}, [%4];" \
        : "=r"(r0), "=r"(r1), "=r"(r2), "=r"(r3) : "r"(addr))

#define MMA16816(d, a, b0v, b1v) \
    asm volatile("mma.sync.aligned.m16n8k16.row.col.f32.f16.f16.f32 " \
        "{%0,%1,%2,%3},{%4,%5,%6,%7},{%8,%9},{%0,%1,%2,%3};" \
        : "+f"((d)[0]), "+f"((d)[1]), "+f"((d)[2]), "+f"((d)[3]) \
        : "r"((a)[0]), "r"((a)[1]), "r"((a)[2]), "r"((a)[3]), "r"(b0v), "r"(b1v))

#define CP_ASYNC16(dst, src) \
    asm volatile("cp.async.cg.shared.global [%0], [%1], 16;" :: "r"(dst), "l"(src))
#define CP_COMMIT() asm volatile("cp.async.commit_group;" ::: "memory")
#define CP_WAIT1()  asm volatile("cp.async.wait_group 1;" ::: "memory")
#define CP_WAIT0()  asm volatile("cp.async.wait_group 0;" ::: "memory")

// ---------------- conversion kernels ----------------
__global__ __launch_bounds__(256) void kconv(const float4* __restrict__ src, int sel)
{
    __half* hi = sel ? g_Kh : g_Qh;
    __half* lo = sel ? g_Kl : g_Ql;
    size_t i = (size_t)blockIdx.x * 256 + threadIdx.x;   // float4 index
    float4 v = src[i];
    size_t e = i * 4;
    __half hx = __float2half_rn(v.x);
    __half hy = __float2half_rn(v.y);
    __half hz = __float2half_rn(v.z);
    __half hw = __float2half_rn(v.w);
    hi[e + 0] = hx; lo[e + 0] = __float2half_rn(v.x - __half2float(hx));
    hi[e + 1] = hy; lo[e + 1] = __float2half_rn(v.y - __half2float(hy));
    hi[e + 2] = hz; lo[e + 2] = __float2half_rn(v.z - __half2float(hz));
    hi[e + 3] = hw; lo[e + 3] = __float2half_rn(v.w - __half2float(hw));
}

// V [b][k][n] -> Vh/Vl transposed [b][n][k]
__global__ __launch_bounds__(256) void ktransV(const float* __restrict__ V)
{
    __shared__ float tile[32][33];
    const int b  = blockIdx.z;
    const int n0 = blockIdx.x * 32;
    const int k0 = blockIdx.y * 32;
    const int tx = threadIdx.x, ty = threadIdx.y;   // (32, 8)
    const float* Vb = V + (size_t)b * SEQ * HID;
    #pragma unroll
    for (int j = 0; j < 4; j++)
        tile[ty + 8 * j][tx] = Vb[(size_t)(k0 + ty + 8 * j) * HID + n0 + tx];
    __syncthreads();
    __half* Hh = g_Vh + (size_t)b * HID * SEQ;
    __half* Hl = g_Vl + (size_t)b * HID * SEQ;
    #pragma unroll
    for (int j = 0; j < 4; j++) {
        float x = tile[tx][ty + 8 * j];
        __half hx = __float2half_rn(x);
        size_t o = (size_t)(n0 + ty + 8 * j) * SEQ + k0 + tx;
        Hh[o] = hx;
        Hl[o] = __float2half_rn(x - __half2float(hx));
    }
}

// ---------------- softmax (fp32 scores -> fp16 hi/lo weights) ----------------
__global__ __launch_bounds__(256) void ksoftmax()
{
    const size_t row = blockIdx.x;
    float* p = g_scores + row * SEQ;
    __half* ph = g_Ph + row * SEQ;
    __half* pl = g_Pl + row * SEQ;
    const int tid = threadIdx.x, lane = tid & 31, warp = tid >> 5;
    __shared__ float red[8];

    float v[8];
    float m = -1e30f;
    #pragma unroll
    for (int i = 0; i < 8; i++) { v[i] = p[tid + i * 256]; m = fmaxf(m, v[i]); }
    #pragma unroll
    for (int off = 16; off > 0; off >>= 1) m = fmaxf(m, __shfl_xor_sync(~0u, m, off));
    if (lane == 0) red[warp] = m;
    __syncthreads();
    float mall = red[0];
    #pragma unroll
    for (int w = 1; w < 8; w++) mall = fmaxf(mall, red[w]);
    __syncthreads();

    float s = 0.f;
    #pragma unroll
    for (int i = 0; i < 8; i++) { v[i] = __expf(v[i] - mall); s += v[i]; }
    #pragma unroll
    for (int off = 16; off > 0; off >>= 1) s += __shfl_xor_sync(~0u, s, off);
    if (lane == 0) red[warp] = s;
    __syncthreads();
    float tot = 0.f;
    #pragma unroll
    for (int w = 0; w < 8; w++) tot += red[w];
    float inv = 1.f / tot;

    #pragma unroll
    for (int i = 0; i < 8; i++) {
        float w = v[i] * inv;
        __half wh = __float2half_rn(w);
        ph[tid + i * 256] = wh;
        pl[tid + i * 256] = __float2half_rn(w - __half2float(wh));
    }
}

// ---------------- mma.sync GEMM:  C[m][n] = sum_k A[m][k]*B[n][k]  (fp16x3) ----------------
// phase 0: A = Qh/Ql, B = Kh/Kl, out = g_scores, epilogue *= scale*sigmoid(span[n])
// phase 1: A = Ph/Pl, B = Vh/Vl, out = O
#define KC    32
#define NCH   (HID / KC)          // 64
#define ROWB  80                  // bytes per smem row (32 halves + 8 pad)
#define BUF   (128 * ROWB)        // 10240
#define STAGE (4 * BUF)           // 40960 : Ah, Al, Bh, Bl
#define SM_GATE (2 * STAGE)       // 81920
#define SM_TOT  (SM_GATE + 512)

__global__ __launch_bounds__(256) void kgemm(int phase, const float* __restrict__ span,
                                             float* __restrict__ outp)
{
    extern __shared__ char smem[];
    const uint32_t su = smem_to_u32(smem);
    const int tid  = threadIdx.x;
    const int lane = tid & 31;
    const int wid  = tid >> 5;
    const int wm   = wid >> 2;       // 0..1, m offset = wm*64
    const int wn   = wid & 3;        // 0..3, n offset = wn*32
    const int b  = blockIdx.z;
    const int m0 = blockIdx.y * 128;
    const int n0 = blockIdx.x * 128;

    const __half* Ahp = (phase ? g_Ph : g_Qh) + (size_t)b * SEQ * HID + (size_t)m0 * HID;
    const __half* Alp = (phase ? g_Pl : g_Ql) + (size_t)b * SEQ * HID + (size_t)m0 * HID;
    const __half* Bhp = (phase ? g_Vh : g_Kh) + (size_t)b * SEQ * HID + (size_t)n0 * HID;
    const __half* Blp = (phase ? g_Vl : g_Kl) + (size_t)b * SEQ * HID + (size_t)n0 * HID;
    float* Cb = phase ? (outp + (size_t)b * SEQ * HID) : (g_scores + (size_t)b * SEQ * SEQ);

    float* gate_s = reinterpret_cast<float*>(smem + SM_GATE);
    if (tid < 128) {
        if (phase == 0) {
            const float scale = 0.02209708691207961f;   // 1/sqrt(2048)
            float sv = span[n0 + tid];
            gate_s[tid] = scale / (1.f + __expf(-sv));
        } else gate_s[tid] = 1.0f;
    }

    const __half* srcs[4] = { Ahp, Alp, Bhp, Blp };

    auto load_stage = [&](int chunk, int s) {
        const int k0 = chunk * KC;
        #pragma unroll
        for (int t = 0; t < 4; t++) {
            const __half* sp = srcs[t];
            uint32_t dbase = su + s * STAGE + t * BUF;
            #pragma unroll
            for (int i = 0; i < 2; i++) {
                int idx = tid + i * 256;          // 0..511
                int row = idx >> 2, seg = idx & 3;
                const void* g = sp + (size_t)row * HID + k0 + seg * 8;
                CP_ASYNC16(dbase + row * ROWB + seg * 16, g);
            }
        }
        CP_COMMIT();
    };

    float acc[4][4][4];
    #pragma unroll
    for (int mi = 0; mi < 4; mi++)
        #pragma unroll
        for (int ni = 0; ni < 4; ni++)
            #pragma unroll
            for (int r = 0; r < 4; r++) acc[mi][ni][r] = 0.f;

    // ldmatrix lane-address components
    const int a_row  = wm * 64 + (lane & 15);            // + mi*16
    const uint32_t a_koff = (uint32_t)((lane >> 4) * 16);
    const int b_row  = wn * 32 + ((lane >> 4) * 8) + (lane & 7);  // + p*16
    const uint32_t b_koff = (uint32_t)(((lane >> 3) & 1) * 16);

    auto compute_stage = [&](int s) {
        const uint32_t base  = su + s * STAGE;
        #pragma unroll
        for (int ks = 0; ks < 2; ks++) {
            const uint32_t ko = ks * 32;
            uint32_t ah[4][4], al[4][4], bh[2][4], bl[2][4];
            #pragma unroll
            for (int mi = 0; mi < 4; mi++) {
                uint32_t ad = base + (uint32_t)((a_row + mi * 16) * ROWB) + ko + a_koff;
                LDSM_X4(ah[mi][0], ah[mi][1], ah[mi][2], ah[mi][3], ad);
                LDSM_X4(al[mi][0], al[mi][1], al[mi][2], al[mi][3], ad + BUF);
            }
            #pragma unroll
            for (int p = 0; p < 2; p++) {
                uint32_t bd = base + 2 * BUF + (uint32_t)((b_row + p * 16) * ROWB) + ko + b_koff;
                LDSM_X4(bh[p][0], bh[p][1], bh[p][2], bh[p][3], bd);
                LDSM_X4(bl[p][0], bl[p][1], bl[p][2], bl[p][3], bd + BUF);
            }
            #pragma unroll
            for (int mi = 0; mi < 4; mi++)
                #pragma unroll
                for (int ni = 0; ni < 4; ni++)
                    MMA16816(acc[mi][ni], ah[mi], bh[ni >> 1][(ni & 1) * 2], bh[ni >> 1][(ni & 1) * 2 + 1]);
            #pragma unroll
            for (int mi = 0; mi < 4; mi++)
                #pragma unroll
                for (int ni = 0; ni < 4; ni++)
                    MMA16816(acc[mi][ni], ah[mi], bl[ni >> 1][(ni & 1) * 2], bl[ni >> 1][(ni & 1) * 2 + 1]);
            #pragma unroll
            for (int mi = 0; mi < 4; mi++)
                #pragma unroll
                for (int ni = 0; ni < 4; ni++)
                    MMA16816(acc[mi][ni], al[mi], bh[ni >> 1][(ni & 1) * 2], bh[ni >> 1][(ni & 1) * 2 + 1]);
        }
    };

    load_stage(0, 0);
    load_stage(1, 1);
    CP_WAIT1();
    __syncthreads();

    for (int c = 0; c < NCH; c++) {
        int s = c & 1;
        compute_stage(s);
        __syncthreads();
        if (c + 2 < NCH) { load_stage(c + 2, s); CP_WAIT1(); }
        else             { CP_WAIT0(); }
        __syncthreads();
    }

    // epilogue
    #pragma unroll
    for (int mi = 0; mi < 4; mi++) {
        int r0 = m0 + wm * 64 + mi * 16 + (lane >> 2);
        #pragma unroll
        for (int ni = 0; ni < 4; ni++) {
            int cloc = wn * 32 + ni * 8 + (lane & 3) * 2;
            float g0 = gate_s[cloc], g1 = gate_s[cloc + 1];
            float2 v0 = make_float2(acc[mi][ni][0] * g0, acc[mi][ni][1] * g1);
            float2 v1 = make_float2(acc[mi][ni][2] * g0, acc[mi][ni][3] * g1);
            *reinterpret_cast<float2*>(&Cb[(size_t)r0 * 2048 + n0 + cloc]) = v0;
            *reinterpret_cast<float2*>(&Cb[(size_t)(r0 + 8) * 2048 + n0 + cloc]) = v1;
        }
    }
}

// -------------------------------------------------------------------------
extern "C" void kernel_launch(void* const* d_in, const int* in_sizes, int n_in,
                              void* d_out, int out_size)
{
    const float* Q    = (const float*)d_in[0];
    const float* K    = (const float*)d_in[1];
    const float* V    = (const float*)d_in[2];
    const float* span = (const float*)d_in[3];
    float* O = (float*)d_out;

    cudaFuncSetAttribute(kgemm, cudaFuncAttributeMaxDynamicSharedMemorySize, SM_TOT);

    const int n4 = (BATCH * SEQ * HID) / 4;          // float4 count
    kconv<<<n4 / 256, 256>>>((const float4*)Q, 0);
    kconv<<<n4 / 256, 256>>>((const float4*)K, 1);
    ktransV<<<dim3(HID / 32, SEQ / 32, BATCH), dim3(32, 8)>>>(V);

    dim3 gridG(SEQ / 128, SEQ / 128, BATCH);
    kgemm<<<gridG, 256, SM_TOT>>>(0, span, nullptr);
    ksoftmax<<<BATCH * SEQ, 256>>>();
    kgemm<<<gridG, 256, SM_TOT>>>(1, nullptr, O);
}

// round 5
// speedup vs baseline: 3.5378x; 1.3749x over previous
#include <cuda_runtime.h>
#include <cuda_fp16.h>
#include <cstdint>
#include <math.h>

#define BATCH 4
#define SEQ   2048
#define HID   2048

// ---------------- static device scratch (no allocations allowed) ----------------
static __device__ float  g_scores[(size_t)BATCH * SEQ * SEQ];   // 64 MB
static __device__ __half g_Qh[(size_t)BATCH * SEQ * HID];
static __device__ __half g_Ql[(size_t)BATCH * SEQ * HID];
static __device__ __half g_Kh[(size_t)BATCH * SEQ * HID];
static __device__ __half g_Vh[(size_t)BATCH * HID * SEQ];       // transposed [b][n][k]
static __device__ __half g_Ph[(size_t)BATCH * SEQ * SEQ];
static __device__ __half g_Pl[(size_t)BATCH * SEQ * SEQ];

// ---------------- helpers ----------------
__device__ __forceinline__ uint32_t smem_to_u32(const void* p) {
    uint32_t a;
    asm("{ .reg .u64 t; cvta.to.shared.u64 t, %1; cvt.u32.u64 %0, t; }" : "=r"(a) : "l"(p));
    return a;
}

#define LDSM_X4(r0, r1, r2, r3, addr) \
    asm volatile("ldmatrix.sync.aligned.m8n8.x4.shared.b16 {%0,%1,%2,%3}, [%4];" \
        : "=r"(r0), "=r"(r1), "=r"(r2), "=r"(r3) : "r"(addr))

#define MMA16816(d, a, b0v, b1v) \
    asm volatile("mma.sync.aligned.m16n8k16.row.col.f32.f16.f16.f32 " \
        "{%0,%1,%2,%3},{%4,%5,%6,%7},{%8,%9},{%0,%1,%2,%3};" \
        : "+f"((d)[0]), "+f"((d)[1]), "+f"((d)[2]), "+f"((d)[3]) \
        : "r"((a)[0]), "r"((a)[1]), "r"((a)[2]), "r"((a)[3]), "r"(b0v), "r"(b1v))

#define CP_ASYNC16(dst, src) \
    asm volatile("cp.async.cg.shared.global [%0], [%1], 16;" :: "r"(dst), "l"(src))
#define CP_COMMIT() asm volatile("cp.async.commit_group;" ::: "memory")
#define CP_WAIT1()  asm volatile("cp.async.wait_group 1;" ::: "memory")
#define CP_WAIT0()  asm volatile("cp.async.wait_group 0;" ::: "memory")

// ---------------- conversion kernels ----------------
// Q: hi + lo (A operand of scores GEMM keeps residual)
__global__ __launch_bounds__(256) void kconvQ(const float4* __restrict__ src)
{
    size_t i = (size_t)blockIdx.x * 256 + threadIdx.x;
    float4 v = src[i];
    size_t e = i * 4;
    __half hx = __float2half_rn(v.x);
    __half hy = __float2half_rn(v.y);
    __half hz = __float2half_rn(v.z);
    __half hw = __float2half_rn(v.w);
    g_Qh[e + 0] = hx; g_Ql[e + 0] = __float2half_rn(v.x - __half2float(hx));
    g_Qh[e + 1] = hy; g_Ql[e + 1] = __float2half_rn(v.y - __half2float(hy));
    g_Qh[e + 2] = hz; g_Ql[e + 2] = __float2half_rn(v.z - __half2float(hz));
    g_Qh[e + 3] = hw; g_Ql[e + 3] = __float2half_rn(v.w - __half2float(hw));
}
// K: hi only (B operand residual dropped)
__global__ __launch_bounds__(256) void kconvK(const float4* __restrict__ src)
{
    size_t i = (size_t)blockIdx.x * 256 + threadIdx.x;
    float4 v = src[i];
    size_t e = i * 4;
    g_Kh[e + 0] = __float2half_rn(v.x);
    g_Kh[e + 1] = __float2half_rn(v.y);
    g_Kh[e + 2] = __float2half_rn(v.z);
    g_Kh[e + 3] = __float2half_rn(v.w);
}

// V [b][k][n] -> Vh transposed [b][n][k]  (hi only)
__global__ __launch_bounds__(256) void ktransV(const float* __restrict__ V)
{
    __shared__ float tile[32][33];
    const int b  = blockIdx.z;
    const int n0 = blockIdx.x * 32;
    const int k0 = blockIdx.y * 32;
    const int tx = threadIdx.x, ty = threadIdx.y;   // (32, 8)
    const float* Vb = V + (size_t)b * SEQ * HID;
    #pragma unroll
    for (int j = 0; j < 4; j++)
        tile[ty + 8 * j][tx] = Vb[(size_t)(k0 + ty + 8 * j) * HID + n0 + tx];
    __syncthreads();
    __half* Hh = g_Vh + (size_t)b * HID * SEQ;
    #pragma unroll
    for (int j = 0; j < 4; j++) {
        float x = tile[tx][ty + 8 * j];
        size_t o = (size_t)(n0 + ty + 8 * j) * SEQ + k0 + tx;
        Hh[o] = __float2half_rn(x);
    }
}

// ---------------- softmax (fp32 scores -> fp16 hi/lo weights) ----------------
__global__ __launch_bounds__(256) void ksoftmax()
{
    const size_t row = blockIdx.x;
    float* p = g_scores + row * SEQ;
    __half* ph = g_Ph + row * SEQ;
    __half* pl = g_Pl + row * SEQ;
    const int tid = threadIdx.x, lane = tid & 31, warp = tid >> 5;
    __shared__ float red[8];

    float v[8];
    float m = -1e30f;
    #pragma unroll
    for (int i = 0; i < 8; i++) { v[i] = p[tid + i * 256]; m = fmaxf(m, v[i]); }
    #pragma unroll
    for (int off = 16; off > 0; off >>= 1) m = fmaxf(m, __shfl_xor_sync(~0u, m, off));
    if (lane == 0) red[warp] = m;
    __syncthreads();
    float mall = red[0];
    #pragma unroll
    for (int w = 1; w < 8; w++) mall = fmaxf(mall, red[w]);
    __syncthreads();

    float s = 0.f;
    #pragma unroll
    for (int i = 0; i < 8; i++) { v[i] = __expf(v[i] - mall); s += v[i]; }
    #pragma unroll
    for (int off = 16; off > 0; off >>= 1) s += __shfl_xor_sync(~0u, s, off);
    if (lane == 0) red[warp] = s;
    __syncthreads();
    float tot = 0.f;
    #pragma unroll
    for (int w = 0; w < 8; w++) tot += red[w];
    float inv = 1.f / tot;

    #pragma unroll
    for (int i = 0; i < 8; i++) {
        float w = v[i] * inv;
        __half wh = __float2half_rn(w);
        ph[tid + i * 256] = wh;
        pl[tid + i * 256] = __float2half_rn(w - __half2float(wh));
    }
}

// ---------------- mma.sync GEMM:  C[m][n] = sum_k A[m][k]*B[n][k]  (fp16 hi+lo A, hi B) ----
// phase 0: A = Qh/Ql, B = Kh, out = g_scores, epilogue *= scale*sigmoid(span[n])
// phase 1: A = Ph/Pl, B = Vh, out = O
#define KC    32
#define NCH   (HID / KC)          // 64
#define ROWB  80                  // bytes per smem row (32 halves + 8 pad)
#define BUF   (128 * ROWB)        // 10240
#define STAGE (3 * BUF)           // 30720 : Ah, Al, Bh
#define NSTG  3
#define SM_GATE (NSTG * STAGE)    // 92160
#define SM_TOT  (SM_GATE + 512)

__global__ __launch_bounds__(256) void kgemm(int phase, const float* __restrict__ span,
                                             float* __restrict__ outp)
{
    extern __shared__ char smem[];
    const uint32_t su = smem_to_u32(smem);
    const int tid  = threadIdx.x;
    const int lane = tid & 31;
    const int wid  = tid >> 5;
    const int wm   = wid >> 2;       // 0..1, m offset = wm*64
    const int wn   = wid & 3;        // 0..3, n offset = wn*32
    const int b  = blockIdx.z;
    const int m0 = blockIdx.y * 128;
    const int n0 = blockIdx.x * 128;

    const __half* Ahp = (phase ? g_Ph : g_Qh) + (size_t)b * SEQ * HID + (size_t)m0 * HID;
    const __half* Alp = (phase ? g_Pl : g_Ql) + (size_t)b * SEQ * HID + (size_t)m0 * HID;
    const __half* Bhp = (phase ? g_Vh : g_Kh) + (size_t)b * SEQ * HID + (size_t)n0 * HID;
    float* Cb = phase ? (outp + (size_t)b * SEQ * HID) : (g_scores + (size_t)b * SEQ * SEQ);

    float* gate_s = reinterpret_cast<float*>(smem + SM_GATE);
    if (tid < 128) {
        if (phase == 0) {
            const float scale = 0.02209708691207961f;   // 1/sqrt(2048)
            float sv = span[n0 + tid];
            gate_s[tid] = scale / (1.f + __expf(-sv));
        } else gate_s[tid] = 1.0f;
    }

    const __half* srcs[3] = { Ahp, Alp, Bhp };

    auto load_stage = [&](int chunk, int s) {
        const int k0 = chunk * KC;
        #pragma unroll
        for (int t = 0; t < 3; t++) {
            const __half* sp = srcs[t];
            uint32_t dbase = su + s * STAGE + t * BUF;
            #pragma unroll
            for (int i = 0; i < 2; i++) {
                int idx = tid + i * 256;          // 0..511
                int row = idx >> 2, seg = idx & 3;
                const void* g = sp + (size_t)row * HID + k0 + seg * 8;
                CP_ASYNC16(dbase + row * ROWB + seg * 16, g);
            }
        }
        CP_COMMIT();
    };

    float acc[4][4][4];
    #pragma unroll
    for (int mi = 0; mi < 4; mi++)
        #pragma unroll
        for (int ni = 0; ni < 4; ni++)
            #pragma unroll
            for (int r = 0; r < 4; r++) acc[mi][ni][r] = 0.f;

    // ldmatrix lane-address components
    const int a_row  = wm * 64 + (lane & 15);                      // + mi*16
    const uint32_t a_koff = (uint32_t)((lane >> 4) * 16);
    const int b_row  = wn * 32 + ((lane >> 4) * 8) + (lane & 7);   // + p*16
    const uint32_t b_koff = (uint32_t)(((lane >> 3) & 1) * 16);

    auto compute_stage = [&](int s) {
        const uint32_t base  = su + s * STAGE;
        #pragma unroll
        for (int ks = 0; ks < 2; ks++) {
            const uint32_t ko = ks * 32;
            uint32_t ah[4][4], al[4][4], bh[2][4];
            #pragma unroll
            for (int mi = 0; mi < 4; mi++) {
                uint32_t ad = base + (uint32_t)((a_row + mi * 16) * ROWB) + ko + a_koff;
                LDSM_X4(ah[mi][0], ah[mi][1], ah[mi][2], ah[mi][3], ad);
                LDSM_X4(al[mi][0], al[mi][1], al[mi][2], al[mi][3], ad + BUF);
            }
            #pragma unroll
            for (int p = 0; p < 2; p++) {
                uint32_t bd = base + 2 * BUF + (uint32_t)((b_row + p * 16) * ROWB) + ko + b_koff;
                LDSM_X4(bh[p][0], bh[p][1], bh[p][2], bh[p][3], bd);
            }
            #pragma unroll
            for (int mi = 0; mi < 4; mi++)
                #pragma unroll
                for (int ni = 0; ni < 4; ni++)
                    MMA16816(acc[mi][ni], ah[mi], bh[ni >> 1][(ni & 1) * 2], bh[ni >> 1][(ni & 1) * 2 + 1]);
            #pragma unroll
            for (int mi = 0; mi < 4; mi++)
                #pragma unroll
                for (int ni = 0; ni < 4; ni++)
                    MMA16816(acc[mi][ni], al[mi], bh[ni >> 1][(ni & 1) * 2], bh[ni >> 1][(ni & 1) * 2 + 1]);
        }
    };

    // 3-stage pipeline, single __syncthreads per chunk
    load_stage(0, 0);
    load_stage(1, 1);

    for (int c = 0; c < NCH; c++) {
        int s = c % NSTG;
        if (c == NCH - 1) { CP_WAIT0(); } else { CP_WAIT1(); }   // load(c) complete
        __syncthreads();                                          // all warps past compute(c-1)
        if (c + 2 < NCH) load_stage(c + 2, (c + 2) % NSTG);       // fill stage freed by compute(c-1)
        compute_stage(s);
    }

    // epilogue
    #pragma unroll
    for (int mi = 0; mi < 4; mi++) {
        int r0 = m0 + wm * 64 + mi * 16 + (lane >> 2);
        #pragma unroll
        for (int ni = 0; ni < 4; ni++) {
            int cloc = wn * 32 + ni * 8 + (lane & 3) * 2;
            float g0 = gate_s[cloc], g1 = gate_s[cloc + 1];
            float2 v0 = make_float2(acc[mi][ni][0] * g0, acc[mi][ni][1] * g1);
            float2 v1 = make_float2(acc[mi][ni][2] * g0, acc[mi][ni][3] * g1);
            *reinterpret_cast<float2*>(&Cb[(size_t)r0 * 2048 + n0 + cloc]) = v0;
            *reinterpret_cast<float2*>(&Cb[(size_t)(r0 + 8) * 2048 + n0 + cloc]) = v1;
        }
    }
}

// -------------------------------------------------------------------------
extern "C" void kernel_launch(void* const* d_in, const int* in_sizes, int n_in,
                              void* d_out, int out_size)
{
    const float* Q    = (const float*)d_in[0];
    const float* K    = (const float*)d_in[1];
    const float* V    = (const float*)d_in[2];
    const float* span = (const float*)d_in[3];
    float* O = (float*)d_out;

    cudaFuncSetAttribute(kgemm, cudaFuncAttributeMaxDynamicSharedMemorySize, SM_TOT);

    const int n4 = (BATCH * SEQ * HID) / 4;          // float4 count
    kconvQ<<<n4 / 256, 256>>>((const float4*)Q);
    kconvK<<<n4 / 256, 256>>>((const float4*)K);
    ktransV<<<dim3(HID / 32, SEQ / 32, BATCH), dim3(32, 8)>>>(V);

    dim3 gridG(SEQ / 128, SEQ / 128, BATCH);
    kgemm<<<gridG, 256, SM_TOT>>>(0, span, nullptr);
    ksoftmax<<<BATCH * SEQ, 256>>>();
    kgemm<<<gridG, 256, SM_TOT>>>(1, nullptr, O);
}

// round 10
// speedup vs baseline: 5.5706x; 1.5746x over previous
#include <cuda_runtime.h>
#include <cuda_fp16.h>
#include <cstdint>
#include <math.h>

#define BATCH 4
#define SEQ   2048
#define HID   2048

// ---------------- static device scratch (no allocations allowed) ----------------
static __device__ float  g_scores[(size_t)BATCH * SEQ * SEQ];   // 64 MB
static __device__ __half g_Qh[(size_t)BATCH * SEQ * HID];
static __device__ __half g_Kh[(size_t)BATCH * SEQ * HID];
static __device__ __half g_Vh[(size_t)BATCH * HID * SEQ];       // transposed [b][n][k]
static __device__ __half g_Ph[(size_t)BATCH * SEQ * SEQ];

// ---------------- helpers ----------------
__device__ __forceinline__ uint32_t smem_to_u32(const void* p) {
    uint32_t a;
    asm("{ .reg .u64 t; cvta.to.shared.u64 t, %1; cvt.u32.u64 %0, t; }" : "=r"(a) : "l"(p));
    return a;
}

#define LDSM_X4(r0, r1, r2, r3, addr) \
    asm volatile("ldmatrix.sync.aligned.m8n8.x4.shared.b16 {%0,%1,%2,%3}, [%4];" \
        : "=r"(r0), "=r"(r1), "=r"(r2), "=r"(r3) : "r"(addr))

#define MMA16816(d, a, b0v, b1v) \
    asm volatile("mma.sync.aligned.m16n8k16.row.col.f32.f16.f16.f32 " \
        "{%0,%1,%2,%3},{%4,%5,%6,%7},{%8,%9},{%0,%1,%2,%3};" \
        : "+f"((d)[0]), "+f"((d)[1]), "+f"((d)[2]), "+f"((d)[3]) \
        : "r"((a)[0]), "r"((a)[1]), "r"((a)[2]), "r"((a)[3]), "r"(b0v), "r"(b1v))

#define CP_ASYNC16(dst, src) \
    asm volatile("cp.async.cg.shared.global [%0], [%1], 16;" :: "r"(dst), "l"(src))
#define CP_COMMIT() asm volatile("cp.async.commit_group;" ::: "memory")
#define CP_WAIT2()  asm volatile("cp.async.wait_group 2;" ::: "memory")
#define CP_WAIT1()  asm volatile("cp.async.wait_group 1;" ::: "memory")
#define CP_WAIT0()  asm volatile("cp.async.wait_group 0;" ::: "memory")

// ---------------- conversion kernels ----------------
// sel: 0 -> g_Qh, 1 -> g_Kh   (destination resolved in DEVICE code; passing a
// __device__ symbol as a host-side kernel arg is UB and was the R5 bug)
__global__ __launch_bounds__(256) void kconv(const float4* __restrict__ src, int sel)
{
    __half* dst = sel ? g_Kh : g_Qh;
    size_t i = (size_t)blockIdx.x * 256 + threadIdx.x;
    float4 v = src[i];
    __half2* d2 = reinterpret_cast<__half2*>(dst + i * 4);
    d2[0] = __floats2half2_rn(v.x, v.y);
    d2[1] = __floats2half2_rn(v.z, v.w);
}

// V [b][k][n] -> Vh transposed [b][n][k]
__global__ __launch_bounds__(256) void ktransV(const float* __restrict__ V)
{
    __shared__ float tile[32][33];
    const int b  = blockIdx.z;
    const int n0 = blockIdx.x * 32;
    const int k0 = blockIdx.y * 32;
    const int tx = threadIdx.x, ty = threadIdx.y;   // (32, 8)
    const float* Vb = V + (size_t)b * SEQ * HID;
    #pragma unroll
    for (int j = 0; j < 4; j++)
        tile[ty + 8 * j][tx] = Vb[(size_t)(k0 + ty + 8 * j) * HID + n0 + tx];
    __syncthreads();
    __half* Hh = g_Vh + (size_t)b * HID * SEQ;
    #pragma unroll
    for (int j = 0; j < 4; j++) {
        float x = tile[tx][ty + 8 * j];
        size_t o = (size_t)(n0 + ty + 8 * j) * SEQ + k0 + tx;
        Hh[o] = __float2half_rn(x);
    }
}

// ---------------- softmax (fp32 scores -> fp16 weights) ----------------
__global__ __launch_bounds__(256) void ksoftmax()
{
    const size_t row = blockIdx.x;
    float* p = g_scores + row * SEQ;
    __half* ph = g_Ph + row * SEQ;
    const int tid = threadIdx.x, lane = tid & 31, warp = tid >> 5;
    __shared__ float red[8];

    float v[8];
    float m = -1e30f;
    #pragma unroll
    for (int i = 0; i < 8; i++) { v[i] = p[tid + i * 256]; m = fmaxf(m, v[i]); }
    #pragma unroll
    for (int off = 16; off > 0; off >>= 1) m = fmaxf(m, __shfl_xor_sync(~0u, m, off));
    if (lane == 0) red[warp] = m;
    __syncthreads();
    float mall = red[0];
    #pragma unroll
    for (int w = 1; w < 8; w++) mall = fmaxf(mall, red[w]);
    __syncthreads();

    float s = 0.f;
    #pragma unroll
    for (int i = 0; i < 8; i++) { v[i] = __expf(v[i] - mall); s += v[i]; }
    #pragma unroll
    for (int off = 16; off > 0; off >>= 1) s += __shfl_xor_sync(~0u, s, off);
    if (lane == 0) red[warp] = s;
    __syncthreads();
    float tot = 0.f;
    #pragma unroll
    for (int w = 0; w < 8; w++) tot += red[w];
    float inv = 1.f / tot;

    #pragma unroll
    for (int i = 0; i < 8; i++)
        ph[tid + i * 256] = __float2half_rn(v[i] * inv);
}

// ---------------- mma.sync GEMM:  C[m][n] = sum_k A[m][k]*B[n][k]  (fp16) ----------------
// phase 0: A = Qh, B = Kh, out = g_scores, epilogue *= scale*sigmoid(span[n])
// phase 1: A = Ph, B = Vh, out = O
#define KC    32
#define NCH   (HID / KC)          // 64
#define ROWB  80                  // bytes per smem row (32 halves + 8 pad)
#define BUF   (128 * ROWB)        // 10240
#define STAGE (2 * BUF)           // 20480 : Ah, Bh
#define NSTG  4
#define SM_GATE (NSTG * STAGE)    // 81920
#define SM_TOT  (SM_GATE + 512)

__global__ __launch_bounds__(256) void kgemm(int phase, const float* __restrict__ span,
                                             float* __restrict__ outp)
{
    extern __shared__ char smem[];
    const uint32_t su = smem_to_u32(smem);
    const int tid  = threadIdx.x;
    const int lane = tid & 31;
    const int wid  = tid >> 5;
    const int wm   = wid >> 2;       // 0..1, m offset = wm*64
    const int wn   = wid & 3;        // 0..3, n offset = wn*32
    const int b  = blockIdx.z;
    const int m0 = blockIdx.y * 128;
    const int n0 = blockIdx.x * 128;

    const __half* Ahp = (phase ? g_Ph : g_Qh) + (size_t)b * SEQ * HID + (size_t)m0 * HID;
    const __half* Bhp = (phase ? g_Vh : g_Kh) + (size_t)b * SEQ * HID + (size_t)n0 * HID;
    float* Cb = phase ? (outp + (size_t)b * SEQ * HID) : (g_scores + (size_t)b * SEQ * SEQ);

    float* gate_s = reinterpret_cast<float*>(smem + SM_GATE);
    if (tid < 128) {
        if (phase == 0) {
            const float scale = 0.02209708691207961f;   // 1/sqrt(2048)
            float sv = span[n0 + tid];
            gate_s[tid] = scale / (1.f + __expf(-sv));
        } else gate_s[tid] = 1.0f;
    }

    auto load_stage = [&](int chunk, int s) {
        const int k0 = chunk * KC;
        uint32_t abase = su + s * STAGE;
        #pragma unroll
        for (int i = 0; i < 2; i++) {
            int idx = tid + i * 256;
            int row = idx >> 2, seg = idx & 3;
            CP_ASYNC16(abase + row * ROWB + seg * 16,
                       Ahp + (size_t)row * HID + k0 + seg * 8);
        }
        uint32_t bbase = abase + BUF;
        #pragma unroll
        for (int i = 0; i < 2; i++) {
            int idx = tid + i * 256;
            int row = idx >> 2, seg = idx & 3;
            CP_ASYNC16(bbase + row * ROWB + seg * 16,
                       Bhp + (size_t)row * HID + k0 + seg * 8);
        }
        CP_COMMIT();
    };

    float acc[4][4][4];
    #pragma unroll
    for (int mi = 0; mi < 4; mi++)
        #pragma unroll
        for (int ni = 0; ni < 4; ni++)
            #pragma unroll
            for (int r = 0; r < 4; r++) acc[mi][ni][r] = 0.f;

    // ldmatrix lane-address components
    const int a_row  = wm * 64 + (lane & 15);                      // + mi*16
    const uint32_t a_koff = (uint32_t)((lane >> 4) * 16);
    const int b_row  = wn * 32 + ((lane >> 4) * 8) + (lane & 7);   // + p*16
    const uint32_t b_koff = (uint32_t)(((lane >> 3) & 1) * 16);

    auto compute_stage = [&](int s) {
        const uint32_t base = su + s * STAGE;
        #pragma unroll
        for (int ks = 0; ks < 2; ks++) {
            const uint32_t ko = ks * 32;
            uint32_t ah[4][4], bh[2][4];
            #pragma unroll
            for (int mi = 0; mi < 4; mi++) {
                uint32_t ad = base + (uint32_t)((a_row + mi * 16) * ROWB) + ko + a_koff;
                LDSM_X4(ah[mi][0], ah[mi][1], ah[mi][2], ah[mi][3], ad);
            }
            #pragma unroll
            for (int p = 0; p < 2; p++) {
                uint32_t bd = base + BUF + (uint32_t)((b_row + p * 16) * ROWB) + ko + b_koff;
                LDSM_X4(bh[p][0], bh[p][1], bh[p][2], bh[p][3], bd);
            }
            #pragma unroll
            for (int mi = 0; mi < 4; mi++)
                #pragma unroll
                for (int ni = 0; ni < 4; ni++)
                    MMA16816(acc[mi][ni], ah[mi], bh[ni >> 1][(ni & 1) * 2], bh[ni >> 1][(ni & 1) * 2 + 1]);
        }
    };

    // 4-stage pipeline, single __syncthreads per chunk
    load_stage(0, 0);
    load_stage(1, 1);
    load_stage(2, 2);

    for (int c = 0; c < NCH; c++) {
        int s = c & 3;
        int rem = NCH - 1 - c;          // loads still in flight beyond chunk c
        if (rem >= 2)      { CP_WAIT2(); }
        else if (rem == 1) { CP_WAIT1(); }
        else               { CP_WAIT0(); }
        __syncthreads();                 // all warps done with compute(c-1) -> stage (c+3)&3 free
        if (c + 3 < NCH) load_stage(c + 3, (c + 3) & 3);
        compute_stage(s);
    }

    // epilogue
    #pragma unroll
    for (int mi = 0; mi < 4; mi++) {
        int r0 = m0 + wm * 64 + mi * 16 + (lane >> 2);
        #pragma unroll
        for (int ni = 0; ni < 4; ni++) {
            int cloc = wn * 32 + ni * 8 + (lane & 3) * 2;
            float g0 = gate_s[cloc], g1 = gate_s[cloc + 1];
            float2 v0 = make_float2(acc[mi][ni][0] * g0, acc[mi][ni][1] * g1);
            float2 v1 = make_float2(acc[mi][ni][2] * g0, acc[mi][ni][3] * g1);
            *reinterpret_cast<float2*>(&Cb[(size_t)r0 * 2048 + n0 + cloc]) = v0;
            *reinterpret_cast<float2*>(&Cb[(size_t)(r0 + 8) * 2048 + n0 + cloc]) = v1;
        }
    }
}

// -------------------------------------------------------------------------
extern "C" void kernel_launch(void* const* d_in, const int* in_sizes, int n_in,
                              void* d_out, int out_size)
{
    const float* Q    = (const float*)d_in[0];
    const float* K    = (const float*)d_in[1];
    const float* V    = (const float*)d_in[2];
    const float* span = (const float*)d_in[3];
    float* O = (float*)d_out;

    cudaFuncSetAttribute(kgemm, cudaFuncAttributeMaxDynamicSharedMemorySize, SM_TOT);

    const int n4 = (BATCH * SEQ * HID) / 4;          // float4 count
    kconv<<<n4 / 256, 256>>>((const float4*)Q, 0);
    kconv<<<n4 / 256, 256>>>((const float4*)K, 1);
    ktransV<<<dim3(HID / 32, SEQ / 32, BATCH), dim3(32, 8)>>>(V);

    dim3 gridG(SEQ / 128, SEQ / 128, BATCH);
    kgemm<<<gridG, 256, SM_TOT>>>(0, span, nullptr);
    ksoftmax<<<BATCH * SEQ, 256>>>();
    kgemm<<<gridG, 256, SM_TOT>>>(1, nullptr, O);
}

// round 12
// speedup vs baseline: 6.3097x; 1.1327x over previous
#include <cuda_runtime.h>
#include <cuda_fp16.h>
#include <cstdint>
#include <math.h>

#define BATCH 4
#define SEQ   2048
#define HID   2048

// ---------------- static device scratch (no allocations allowed) ----------------
static __device__ float  g_scores[(size_t)BATCH * SEQ * SEQ];   // 64 MB
static __device__ __half g_Qh[(size_t)BATCH * SEQ * HID];
static __device__ __half g_Kh[(size_t)BATCH * SEQ * HID];
static __device__ __half g_Vh[(size_t)BATCH * HID * SEQ];       // transposed [b][n][k]
static __device__ __half g_Ph[(size_t)BATCH * SEQ * SEQ];

// ---------------- helpers ----------------
__device__ __forceinline__ uint32_t smem_to_u32(const void* p) {
    uint32_t a;
    asm("{ .reg .u64 t; cvta.to.shared.u64 t, %1; cvt.u32.u64 %0, t; }" : "=r"(a) : "l"(p));
    return a;
}

#define LDSM_X4(r0, r1, r2, r3, addr) \
    asm volatile("ldmatrix.sync.aligned.m8n8.x4.shared.b16 {%0,%1,%2,%3}, [%4];" \
        : "=r"(r0), "=r"(r1), "=r"(r2), "=r"(r3) : "r"(addr))

#define MMA16816(d, a, b0v, b1v) \
    asm volatile("mma.sync.aligned.m16n8k16.row.col.f32.f16.f16.f32 " \
        "{%0,%1,%2,%3},{%4,%5,%6,%7},{%8,%9},{%0,%1,%2,%3};" \
        : "+f"((d)[0]), "+f"((d)[1]), "+f"((d)[2]), "+f"((d)[3]) \
        : "r"((a)[0]), "r"((a)[1]), "r"((a)[2]), "r"((a)[3]), "r"(b0v), "r"(b1v))

#define CP_ASYNC16(dst, src) \
    asm volatile("cp.async.cg.shared.global [%0], [%1], 16;" :: "r"(dst), "l"(src))
#define CP_COMMIT() asm volatile("cp.async.commit_group;" ::: "memory")
#define CP_WAIT1()  asm volatile("cp.async.wait_group 1;" ::: "memory")
#define CP_WAIT0()  asm volatile("cp.async.wait_group 0;" ::: "memory")

// ---------------- conversion kernels ----------------
// sel: 0 -> g_Qh, 1 -> g_Kh  (destination resolved in device code)
__global__ __launch_bounds__(256) void kconv(const float4* __restrict__ src, int sel)
{
    __half* dst = sel ? g_Kh : g_Qh;
    size_t i = (size_t)blockIdx.x * 256 + threadIdx.x;
    float4 v = src[i];
    __half2* d2 = reinterpret_cast<__half2*>(dst + i * 4);
    d2[0] = __floats2half2_rn(v.x, v.y);
    d2[1] = __floats2half2_rn(v.z, v.w);
}

// V [b][k][n] -> Vh transposed [b][n][k]
__global__ __launch_bounds__(256) void ktransV(const float* __restrict__ V)
{
    __shared__ float tile[32][33];
    const int b  = blockIdx.z;
    const int n0 = blockIdx.x * 32;
    const int k0 = blockIdx.y * 32;
    const int tx = threadIdx.x, ty = threadIdx.y;   // (32, 8)
    const float* Vb = V + (size_t)b * SEQ * HID;
    #pragma unroll
    for (int j = 0; j < 4; j++)
        tile[ty + 8 * j][tx] = Vb[(size_t)(k0 + ty + 8 * j) * HID + n0 + tx];
    __syncthreads();
    __half* Hh = g_Vh + (size_t)b * HID * SEQ;
    #pragma unroll
    for (int j = 0; j < 4; j++) {
        float x = tile[tx][ty + 8 * j];
        size_t o = (size_t)(n0 + ty + 8 * j) * SEQ + k0 + tx;
        Hh[o] = __float2half_rn(x);
    }
}

// ---------------- softmax (fp32 scores -> fp16 weights) ----------------
__global__ __launch_bounds__(256) void ksoftmax()
{
    const size_t row = blockIdx.x;
    float* p = g_scores + row * SEQ;
    __half* ph = g_Ph + row * SEQ;
    const int tid = threadIdx.x, lane = tid & 31, warp = tid >> 5;
    __shared__ float red[8];

    float v[8];
    float m = -1e30f;
    #pragma unroll
    for (int i = 0; i < 8; i++) { v[i] = p[tid + i * 256]; m = fmaxf(m, v[i]); }
    #pragma unroll
    for (int off = 16; off > 0; off >>= 1) m = fmaxf(m, __shfl_xor_sync(~0u, m, off));
    if (lane == 0) red[warp] = m;
    __syncthreads();
    float mall = red[0];
    #pragma unroll
    for (int w = 1; w < 8; w++) mall = fmaxf(mall, red[w]);
    __syncthreads();

    float s = 0.f;
    #pragma unroll
    for (int i = 0; i < 8; i++) { v[i] = __expf(v[i] - mall); s += v[i]; }
    #pragma unroll
    for (int off = 16; off > 0; off >>= 1) s += __shfl_xor_sync(~0u, s, off);
    if (lane == 0) red[warp] = s;
    __syncthreads();
    float tot = 0.f;
    #pragma unroll
    for (int w = 0; w < 8; w++) tot += red[w];
    float inv = 1.f / tot;

    #pragma unroll
    for (int i = 0; i < 8; i++)
        ph[tid + i * 256] = __float2half_rn(v[i] * inv);
}

// ---------------- mma.sync GEMM:  C[m][n] = sum_k A[m][k]*B[n][k]  (fp16) ----------------
// phase 0: A = Qh, B = Kh, out = g_scores, epilogue *= scale*sigmoid(span[n])
// phase 1: A = Ph, B = Vh, out = O
#define KC    32
#define NCH   (HID / KC)          // 64
#define ROWB  80                  // bytes per smem row (32 halves + 8 pad)
#define BUF   (128 * ROWB)        // 10240
#define STAGE (2 * BUF)           // 20480 : Ah, Bh
#define NSTG  4
#define SM_GATE (NSTG * STAGE)    // 81920
#define SM_TOT  (SM_GATE + 512)

__global__ __launch_bounds__(256, 2) void kgemm(int phase, const float* __restrict__ span,
                                                float* __restrict__ outp)
{
    extern __shared__ char smem[];
    const uint32_t su = smem_to_u32(smem);
    const int tid  = threadIdx.x;
    const int lane = tid & 31;
    const int wid  = tid >> 5;
    const int wm   = wid >> 2;       // 0..1, m offset = wm*64
    const int wn   = wid & 3;        // 0..3, n offset = wn*32
    const int b  = blockIdx.z;
    const int m0 = blockIdx.y * 128;
    const int n0 = blockIdx.x * 128;

    const __half* Ahp = (phase ? g_Ph : g_Qh) + (size_t)b * SEQ * HID + (size_t)m0 * HID;
    const __half* Bhp = (phase ? g_Vh : g_Kh) + (size_t)b * SEQ * HID + (size_t)n0 * HID;
    float* Cb = phase ? (outp + (size_t)b * SEQ * HID) : (g_scores + (size_t)b * SEQ * SEQ);

    float* gate_s = reinterpret_cast<float*>(smem + SM_GATE);
    if (tid < 128) {
        if (phase == 0) {
            const float scale = 0.02209708691207961f;   // 1/sqrt(2048)
            float sv = span[n0 + tid];
            gate_s[tid] = scale / (1.f + __expf(-sv));
        } else gate_s[tid] = 1.0f;
    }

    auto load_stage = [&](int chunk, int s) {
        const int k0 = chunk * KC;
        uint32_t abase = su + s * STAGE;
        #pragma unroll
        for (int i = 0; i < 2; i++) {
            int idx = tid + i * 256;
            int row = idx >> 2, seg = idx & 3;
            CP_ASYNC16(abase + row * ROWB + seg * 16,
                       Ahp + (size_t)row * HID + k0 + seg * 8);
        }
        uint32_t bbase = abase + BUF;
        #pragma unroll
        for (int i = 0; i < 2; i++) {
            int idx = tid + i * 256;
            int row = idx >> 2, seg = idx & 3;
            CP_ASYNC16(bbase + row * ROWB + seg * 16,
                       Bhp + (size_t)row * HID + k0 + seg * 8);
        }
        CP_COMMIT();
    };

    float acc[4][4][4];
    #pragma unroll
    for (int mi = 0; mi < 4; mi++)
        #pragma unroll
        for (int ni = 0; ni < 4; ni++)
            #pragma unroll
            for (int r = 0; r < 4; r++) acc[mi][ni][r] = 0.f;

    // double-buffered fragments (buffer index = slice parity, compile-time)
    uint32_t ahf[2][4][4], bhf[2][2][4];

    // ldmatrix lane-address components
    const int a_row  = wm * 64 + (lane & 15);                      // + mi*16
    const uint32_t a_koff = (uint32_t)((lane >> 4) * 16);
    const int b_row  = wn * 32 + ((lane >> 4) * 8) + (lane & 7);   // + p*16
    const uint32_t b_koff = (uint32_t)(((lane >> 3) & 1) * 16);

    #define LDSM_SLICE(chunk, ks, bf) do {                                              \
        const uint32_t _base = su + (uint32_t)(((chunk) & 3) * STAGE);                  \
        const uint32_t _ko = (uint32_t)((ks) * 32);                                     \
        _Pragma("unroll")                                                               \
        for (int p = 0; p < 2; p++) {                                                   \
            uint32_t bd = _base + BUF + (uint32_t)((b_row + p * 16) * ROWB) + _ko + b_koff; \
            LDSM_X4(bhf[bf][p][0], bhf[bf][p][1], bhf[bf][p][2], bhf[bf][p][3], bd);    \
        }                                                                               \
        _Pragma("unroll")                                                               \
        for (int mi = 0; mi < 4; mi++) {                                                \
            uint32_t ad = _base + (uint32_t)((a_row + mi * 16) * ROWB) + _ko + a_koff;  \
            LDSM_X4(ahf[bf][mi][0], ahf[bf][mi][1], ahf[bf][mi][2], ahf[bf][mi][3], ad);\
        }                                                                               \
    } while (0)

    #define MMA_SLICE(bf) do {                                                          \
        _Pragma("unroll")                                                               \
        for (int mi = 0; mi < 4; mi++)                                                  \
            _Pragma("unroll")                                                           \
            for (int ni = 0; ni < 4; ni++)                                              \
                MMA16816(acc[mi][ni], ahf[bf][mi],                                      \
                         bhf[bf][ni >> 1][(ni & 1) * 2],                                \
                         bhf[bf][ni >> 1][(ni & 1) * 2 + 1]);                           \
    } while (0)

    // prologue: 3 stages in flight
    load_stage(0, 0);
    load_stage(1, 1);
    load_stage(2, 2);

    for (int c = 0; c < NCH; c++) {
        // guarantee chunks <= c+1 resident (prefetch below reads chunk c+1)
        if (c >= NCH - 2) { CP_WAIT0(); } else { CP_WAIT1(); }
        __syncthreads();                      // visibility + protect stage (c+3)&3 overwrite
        if (c + 3 < NCH) load_stage(c + 3, (c + 3) & 3);

        if (c == 0) LDSM_SLICE(0, 0, 0);      // prime the fragment pipeline

        // slice 0: prefetch slice 1 of this chunk, MMA on buffer 0
        LDSM_SLICE(c, 1, 1);
        MMA_SLICE(0);
        // slice 1: prefetch slice 0 of next chunk (data already resident), MMA on buffer 1
        if (c + 1 < NCH) LDSM_SLICE(c + 1, 0, 0);
        MMA_SLICE(1);
    }

    // epilogue
    #pragma unroll
    for (int mi = 0; mi < 4; mi++) {
        int r0 = m0 + wm * 64 + mi * 16 + (lane >> 2);
        #pragma unroll
        for (int ni = 0; ni < 4; ni++) {
            int cloc = wn * 32 + ni * 8 + (lane & 3) * 2;
            float g0 = gate_s[cloc], g1 = gate_s[cloc + 1];
            float2 v0 = make_float2(acc[mi][ni][0] * g0, acc[mi][ni][1] * g1);
            float2 v1 = make_float2(acc[mi][ni][2] * g0, acc[mi][ni][3] * g1);
            *reinterpret_cast<float2*>(&Cb[(size_t)r0 * 2048 + n0 + cloc]) = v0;
            *reinterpret_cast<float2*>(&Cb[(size_t)(r0 + 8) * 2048 + n0 + cloc]) = v1;
        }
    }
}

// -------------------------------------------------------------------------
extern "C" void kernel_launch(void* const* d_in, const int* in_sizes, int n_in,
                              void* d_out, int out_size)
{
    const float* Q    = (const float*)d_in[0];
    const float* K    = (const float*)d_in[1];
    const float* V    = (const float*)d_in[2];
    const float* span = (const float*)d_in[3];
    float* O = (float*)d_out;

    cudaFuncSetAttribute(kgemm, cudaFuncAttributeMaxDynamicSharedMemorySize, SM_TOT);

    const int n4 = (BATCH * SEQ * HID) / 4;          // float4 count
    kconv<<<n4 / 256, 256>>>((const float4*)Q, 0);
    kconv<<<n4 / 256, 256>>>((const float4*)K, 1);
    ktransV<<<dim3(HID / 32, SEQ / 32, BATCH), dim3(32, 8)>>>(V);

    dim3 gridG(SEQ / 128, SEQ / 128, BATCH);
    kgemm<<<gridG, 256, SM_TOT>>>(0, span, nullptr);
    ksoftmax<<<BATCH * SEQ, 256>>>();
    kgemm<<<gridG, 256, SM_TOT>>>(1, nullptr, O);
}

// round 13
// speedup vs baseline: 6.7097x; 1.0634x over previous
#include <cuda_runtime.h>
#include <cuda_fp16.h>
#include <cstdint>
#include <math.h>

#define BATCH 4
#define SEQ   2048
#define HID   2048

// ---------------- static device scratch (no allocations allowed) ----------------
static __device__ float  g_scores[(size_t)BATCH * SEQ * SEQ];   // 64 MB
static __device__ __half g_Qh[(size_t)BATCH * SEQ * HID];
static __device__ __half g_Kh[(size_t)BATCH * SEQ * HID];
static __device__ __half g_Vh[(size_t)BATCH * HID * SEQ];       // transposed [b][n][k]
static __device__ __half g_Ph[(size_t)BATCH * SEQ * SEQ];

// ---------------- helpers ----------------
__device__ __forceinline__ uint32_t smem_to_u32(const void* p) {
    uint32_t a;
    asm("{ .reg .u64 t; cvta.to.shared.u64 t, %1; cvt.u32.u64 %0, t; }" : "=r"(a) : "l"(p));
    return a;
}

#define LDSM_X4(r0, r1, r2, r3, addr) \
    asm volatile("ldmatrix.sync.aligned.m8n8.x4.shared.b16 {%0,%1,%2,%3}, [%4];" \
        : "=r"(r0), "=r"(r1), "=r"(r2), "=r"(r3) : "r"(addr))

#define MMA16816(d, a, b0v, b1v) \
    asm volatile("mma.sync.aligned.m16n8k16.row.col.f32.f16.f16.f32 " \
        "{%0,%1,%2,%3},{%4,%5,%6,%7},{%8,%9},{%0,%1,%2,%3};" \
        : "+f"((d)[0]), "+f"((d)[1]), "+f"((d)[2]), "+f"((d)[3]) \
        : "r"((a)[0]), "r"((a)[1]), "r"((a)[2]), "r"((a)[3]), "r"(b0v), "r"(b1v))

#define CP_ASYNC16(dst, src) \
    asm volatile("cp.async.cg.shared.global [%0], [%1], 16;" :: "r"(dst), "l"(src))
#define CP_COMMIT() asm volatile("cp.async.commit_group;" ::: "memory")
#define CP_WAIT1()  asm volatile("cp.async.wait_group 1;" ::: "memory")
#define CP_WAIT0()  asm volatile("cp.async.wait_group 0;" ::: "memory")

// ---------------- conversion kernels ----------------
// sel: 0 -> g_Qh, 1 -> g_Kh  (destination resolved in device code)
__global__ __launch_bounds__(256) void kconv(const float4* __restrict__ src, int sel)
{
    __half* dst = sel ? g_Kh : g_Qh;
    size_t i = (size_t)blockIdx.x * 256 + threadIdx.x;
    float4 v = src[i];
    __half2* d2 = reinterpret_cast<__half2*>(dst + i * 4);
    d2[0] = __floats2half2_rn(v.x, v.y);
    d2[1] = __floats2half2_rn(v.z, v.w);
}

// V [b][k][n] -> Vh transposed [b][n][k]
__global__ __launch_bounds__(256) void ktransV(const float* __restrict__ V)
{
    __shared__ float tile[32][33];
    const int b  = blockIdx.z;
    const int n0 = blockIdx.x * 32;
    const int k0 = blockIdx.y * 32;
    const int tx = threadIdx.x, ty = threadIdx.y;   // (32, 8)
    const float* Vb = V + (size_t)b * SEQ * HID;
    #pragma unroll
    for (int j = 0; j < 4; j++)
        tile[ty + 8 * j][tx] = Vb[(size_t)(k0 + ty + 8 * j) * HID + n0 + tx];
    __syncthreads();
    __half* Hh = g_Vh + (size_t)b * HID * SEQ;
    #pragma unroll
    for (int j = 0; j < 4; j++) {
        float x = tile[tx][ty + 8 * j];
        size_t o = (size_t)(n0 + ty + 8 * j) * SEQ + k0 + tx;
        Hh[o] = __float2half_rn(x);
    }
}

// ---------------- softmax (fp32 scores -> fp16 weights) ----------------
__global__ __launch_bounds__(256) void ksoftmax()
{
    const size_t row = blockIdx.x;
    float* p = g_scores + row * SEQ;
    __half* ph = g_Ph + row * SEQ;
    const int tid = threadIdx.x, lane = tid & 31, warp = tid >> 5;
    __shared__ float red[8];

    float v[8];
    float m = -1e30f;
    #pragma unroll
    for (int i = 0; i < 8; i++) { v[i] = p[tid + i * 256]; m = fmaxf(m, v[i]); }
    #pragma unroll
    for (int off = 16; off > 0; off >>= 1) m = fmaxf(m, __shfl_xor_sync(~0u, m, off));
    if (lane == 0) red[warp] = m;
    __syncthreads();
    float mall = red[0];
    #pragma unroll
    for (int w = 1; w < 8; w++) mall = fmaxf(mall, red[w]);
    __syncthreads();

    float s = 0.f;
    #pragma unroll
    for (int i = 0; i < 8; i++) { v[i] = __expf(v[i] - mall); s += v[i]; }
    #pragma unroll
    for (int off = 16; off > 0; off >>= 1) s += __shfl_xor_sync(~0u, s, off);
    if (lane == 0) red[warp] = s;
    __syncthreads();
    float tot = 0.f;
    #pragma unroll
    for (int w = 0; w < 8; w++) tot += red[w];
    float inv = 1.f / tot;

    #pragma unroll
    for (int i = 0; i < 8; i++)
        ph[tid + i * 256] = __float2half_rn(v[i] * inv);
}

// ---------------- mma.sync GEMM:  C[m][n] = sum_k A[m][k]*B[n][k]  (fp16) ----------------
// phase 0: A = Qh, B = Kh, out = g_scores, epilogue *= scale*sigmoid(span[n])
// phase 1: A = Ph, B = Vh, out = O
#define KC    64
#define NCH   (HID / KC)          // 32
#define NSLC  4                   // k-slices of 16 per chunk
#define ROWB  144                 // bytes per smem row (64 halves + 16 pad)
#define BUF   (128 * ROWB)        // 18432
#define STAGE (2 * BUF)           // 36864 : Ah, Bh
#define NSTG  3
#define SM_GATE (NSTG * STAGE)    // 110592
#define SM_TOT  (SM_GATE + 512)

__global__ __launch_bounds__(256, 2) void kgemm(int phase, const float* __restrict__ span,
                                                float* __restrict__ outp)
{
    extern __shared__ char smem[];
    const uint32_t su = smem_to_u32(smem);
    const int tid  = threadIdx.x;
    const int lane = tid & 31;
    const int wid  = tid >> 5;
    const int wm   = wid >> 2;       // 0..1, m offset = wm*64
    const int wn   = wid & 3;        // 0..3, n offset = wn*32
    const int b  = blockIdx.z;
    const int m0 = blockIdx.y * 128;
    const int n0 = blockIdx.x * 128;

    const __half* Ahp = (phase ? g_Ph : g_Qh) + (size_t)b * SEQ * HID + (size_t)m0 * HID;
    const __half* Bhp = (phase ? g_Vh : g_Kh) + (size_t)b * SEQ * HID + (size_t)n0 * HID;
    float* Cb = phase ? (outp + (size_t)b * SEQ * HID) : (g_scores + (size_t)b * SEQ * SEQ);

    float* gate_s = reinterpret_cast<float*>(smem + SM_GATE);
    if (tid < 128) {
        if (phase == 0) {
            const float scale = 0.02209708691207961f;   // 1/sqrt(2048)
            float sv = span[n0 + tid];
            gate_s[tid] = scale / (1.f + __expf(-sv));
        } else gate_s[tid] = 1.0f;
    }

    // 64 halves per row = 128 B: each thread copies 4 x 16B rows-segments per buffer
    auto load_stage = [&](int chunk, int s) {
        const int k0 = chunk * KC;
        uint32_t abase = su + (uint32_t)(s * STAGE);
        #pragma unroll
        for (int i = 0; i < 4; i++) {
            int idx = tid + i * 256;          // 0..1023
            int row = idx >> 3, seg = idx & 7;
            CP_ASYNC16(abase + row * ROWB + seg * 16,
                       Ahp + (size_t)row * HID + k0 + seg * 8);
        }
        uint32_t bbase = abase + BUF;
        #pragma unroll
        for (int i = 0; i < 4; i++) {
            int idx = tid + i * 256;
            int row = idx >> 3, seg = idx & 7;
            CP_ASYNC16(bbase + row * ROWB + seg * 16,
                       Bhp + (size_t)row * HID + k0 + seg * 8);
        }
        CP_COMMIT();
    };

    float acc[4][4][4];
    #pragma unroll
    for (int mi = 0; mi < 4; mi++)
        #pragma unroll
        for (int ni = 0; ni < 4; ni++)
            #pragma unroll
            for (int r = 0; r < 4; r++) acc[mi][ni][r] = 0.f;

    // double-buffered fragments (buffer index = slice parity, compile-time)
    uint32_t ahf[2][4][4], bhf[2][2][4];

    // ldmatrix lane-address components
    const int a_row  = wm * 64 + (lane & 15);                      // + mi*16
    const uint32_t a_koff = (uint32_t)((lane >> 4) * 16);
    const int b_row  = wn * 32 + ((lane >> 4) * 8) + (lane & 7);   // + p*16
    const uint32_t b_koff = (uint32_t)(((lane >> 3) & 1) * 16);

    #define LDSM_SLICE(stg, ks, bf) do {                                                \
        const uint32_t _base = su + (uint32_t)((stg) * STAGE);                          \
        const uint32_t _ko = (uint32_t)((ks) * 32);                                     \
        _Pragma("unroll")                                                               \
        for (int p = 0; p < 2; p++) {                                                   \
            uint32_t bd = _base + BUF + (uint32_t)((b_row + p * 16) * ROWB) + _ko + b_koff; \
            LDSM_X4(bhf[bf][p][0], bhf[bf][p][1], bhf[bf][p][2], bhf[bf][p][3], bd);    \
        }                                                                               \
        _Pragma("unroll")                                                               \
        for (int mi = 0; mi < 4; mi++) {                                                \
            uint32_t ad = _base + (uint32_t)((a_row + mi * 16) * ROWB) + _ko + a_koff;  \
            LDSM_X4(ahf[bf][mi][0], ahf[bf][mi][1], ahf[bf][mi][2], ahf[bf][mi][3], ad);\
        }                                                                               \
    } while (0)

    #define MMA_SLICE(bf) do {                                                          \
        _Pragma("unroll")                                                               \
        for (int mi = 0; mi < 4; mi++)                                                  \
            _Pragma("unroll")                                                           \
            for (int ni = 0; ni < 4; ni++)                                              \
                MMA16816(acc[mi][ni], ahf[bf][mi],                                      \
                         bhf[bf][ni >> 1][(ni & 1) * 2],                                \
                         bhf[bf][ni >> 1][(ni & 1) * 2 + 1]);                           \
    } while (0)

    // prologue: 2 stages in flight
    load_stage(0, 0);
    load_stage(1, 1);

    int s = 0;          // stage of chunk c
    for (int c = 0; c < NCH; c++) {
        if (c == NCH - 1) { CP_WAIT0(); } else { CP_WAIT1(); }   // chunk c resident
        __syncthreads();                  // protect stage being overwritten below
        if (c + 2 < NCH) {
            int s2 = s + 2; if (s2 >= NSTG) s2 -= NSTG;
            load_stage(c + 2, s2);
        }

        // 4-slice fragment pipeline: only slice 0's LDSM is exposed
        LDSM_SLICE(s, 0, 0);
        LDSM_SLICE(s, 1, 1);
        MMA_SLICE(0);
        LDSM_SLICE(s, 2, 0);
        MMA_SLICE(1);
        LDSM_SLICE(s, 3, 1);
        MMA_SLICE(0);
        MMA_SLICE(1);

        if (++s == NSTG) s = 0;
    }

    // epilogue
    #pragma unroll
    for (int mi = 0; mi < 4; mi++) {
        int r0 = m0 + wm * 64 + mi * 16 + (lane >> 2);
        #pragma unroll
        for (int ni = 0; ni < 4; ni++) {
            int cloc = wn * 32 + ni * 8 + (lane & 3) * 2;
            float g0 = gate_s[cloc], g1 = gate_s[cloc + 1];
            float2 v0 = make_float2(acc[mi][ni][0] * g0, acc[mi][ni][1] * g1);
            float2 v1 = make_float2(acc[mi][ni][2] * g0, acc[mi][ni][3] * g1);
            *reinterpret_cast<float2*>(&Cb[(size_t)r0 * 2048 + n0 + cloc]) = v0;
            *reinterpret_cast<float2*>(&Cb[(size_t)(r0 + 8) * 2048 + n0 + cloc]) = v1;
        }
    }
}

// -------------------------------------------------------------------------
extern "C" void kernel_launch(void* const* d_in, const int* in_sizes, int n_in,
                              void* d_out, int out_size)
{
    const float* Q    = (const float*)d_in[0];
    const float* K    = (const float*)d_in[1];
    const float* V    = (const float*)d_in[2];
    const float* span = (const float*)d_in[3];
    float* O = (float*)d_out;

    cudaFuncSetAttribute(kgemm, cudaFuncAttributeMaxDynamicSharedMemorySize, SM_TOT);

    const int n4 = (BATCH * SEQ * HID) / 4;          // float4 count
    kconv<<<n4 / 256, 256>>>((const float4*)Q, 0);
    kconv<<<n4 / 256, 256>>>((const float4*)K, 1);
    ktransV<<<dim3(HID / 32, SEQ / 32, BATCH), dim3(32, 8)>>>(V);

    dim3 gridG(SEQ / 128, SEQ / 128, BATCH);
    kgemm<<<gridG, 256, SM_TOT>>>(0, span, nullptr);
    ksoftmax<<<BATCH * SEQ, 256>>>();
    kgemm<<<gridG, 256, SM_TOT>>>(1, nullptr, O);
}

// round 14
// speedup vs baseline: 6.9508x; 1.0359x over previous
#include <cuda_runtime.h>
#include <cuda_fp16.h>
#include <cstdint>
#include <math.h>

#define BATCH 4
#define SEQ   2048
#define HID   2048

// ---------------- static device scratch (no allocations allowed) ----------------
static __device__ float  g_scores[(size_t)BATCH * SEQ * SEQ];   // 64 MB
static __device__ __half g_Qh[(size_t)BATCH * SEQ * HID];
static __device__ __half g_Kh[(size_t)BATCH * SEQ * HID];
static __device__ __half g_Vh[(size_t)BATCH * HID * SEQ];       // transposed [b][n][k]
static __device__ __half g_Ph[(size_t)BATCH * SEQ * SEQ];

// ---------------- helpers ----------------
__device__ __forceinline__ uint32_t smem_to_u32(const void* p) {
    uint32_t a;
    asm("{ .reg .u64 t; cvta.to.shared.u64 t, %1; cvt.u32.u64 %0, t; }" : "=r"(a) : "l"(p));
    return a;
}

#define LDSM_X4(r0, r1, r2, r3, addr) \
    asm volatile("ldmatrix.sync.aligned.m8n8.x4.shared.b16 {%0,%1,%2,%3}, [%4];" \
        : "=r"(r0), "=r"(r1), "=r"(r2), "=r"(r3) : "r"(addr))

#define MMA16816(d, a, b0v, b1v) \
    asm volatile("mma.sync.aligned.m16n8k16.row.col.f32.f16.f16.f32 " \
        "{%0,%1,%2,%3},{%4,%5,%6,%7},{%8,%9},{%0,%1,%2,%3};" \
        : "+f"((d)[0]), "+f"((d)[1]), "+f"((d)[2]), "+f"((d)[3]) \
        : "r"((a)[0]), "r"((a)[1]), "r"((a)[2]), "r"((a)[3]), "r"(b0v), "r"(b1v))

#define CP_ASYNC16(dst, src) \
    asm volatile("cp.async.cg.shared.global [%0], [%1], 16;" :: "r"(dst), "l"(src))
#define CP_COMMIT() asm volatile("cp.async.commit_group;" ::: "memory")
#define CP_WAIT0()  asm volatile("cp.async.wait_group 0;" ::: "memory")

// ---------------- conversion kernels ----------------
// sel: 0 -> g_Qh, 1 -> g_Kh  (destination resolved in device code)
__global__ __launch_bounds__(256) void kconv(const float4* __restrict__ src, int sel)
{
    __half* dst = sel ? g_Kh : g_Qh;
    size_t i = (size_t)blockIdx.x * 256 + threadIdx.x;
    float4 v = src[i];
    __half2* d2 = reinterpret_cast<__half2*>(dst + i * 4);
    d2[0] = __floats2half2_rn(v.x, v.y);
    d2[1] = __floats2half2_rn(v.z, v.w);
}

// V [b][k][n] -> Vh transposed [b][n][k]
__global__ __launch_bounds__(256) void ktransV(const float* __restrict__ V)
{
    __shared__ float tile[32][33];
    const int b  = blockIdx.z;
    const int n0 = blockIdx.x * 32;
    const int k0 = blockIdx.y * 32;
    const int tx = threadIdx.x, ty = threadIdx.y;   // (32, 8)
    const float* Vb = V + (size_t)b * SEQ * HID;
    #pragma unroll
    for (int j = 0; j < 4; j++)
        tile[ty + 8 * j][tx] = Vb[(size_t)(k0 + ty + 8 * j) * HID + n0 + tx];
    __syncthreads();
    __half* Hh = g_Vh + (size_t)b * HID * SEQ;
    #pragma unroll
    for (int j = 0; j < 4; j++) {
        float x = tile[tx][ty + 8 * j];
        size_t o = (size_t)(n0 + ty + 8 * j) * SEQ + k0 + tx;
        Hh[o] = __float2half_rn(x);
    }
}

// ---------------- softmax (fp32 scores -> fp16 weights), vectorized ----------------
__global__ __launch_bounds__(256) void ksoftmax()
{
    const size_t row = blockIdx.x;
    const float4* p4 = reinterpret_cast<const float4*>(g_scores + row * SEQ);
    __half* ph = g_Ph + row * SEQ;
    const int tid = threadIdx.x, lane = tid & 31, warp = tid >> 5;
    __shared__ float red[8];

    float4 v[2];
    v[0] = p4[tid];
    v[1] = p4[tid + 256];
    float m = fmaxf(fmaxf(v[0].x, v[0].y), fmaxf(v[0].z, v[0].w));
    m = fmaxf(m, fmaxf(fmaxf(v[1].x, v[1].y), fmaxf(v[1].z, v[1].w)));
    #pragma unroll
    for (int off = 16; off > 0; off >>= 1) m = fmaxf(m, __shfl_xor_sync(~0u, m, off));
    if (lane == 0) red[warp] = m;
    __syncthreads();
    float mall = red[0];
    #pragma unroll
    for (int w = 1; w < 8; w++) mall = fmaxf(mall, red[w]);
    __syncthreads();

    float s = 0.f;
    #pragma unroll
    for (int i = 0; i < 2; i++) {
        v[i].x = __expf(v[i].x - mall); s += v[i].x;
        v[i].y = __expf(v[i].y - mall); s += v[i].y;
        v[i].z = __expf(v[i].z - mall); s += v[i].z;
        v[i].w = __expf(v[i].w - mall); s += v[i].w;
    }
    #pragma unroll
    for (int off = 16; off > 0; off >>= 1) s += __shfl_xor_sync(~0u, s, off);
    if (lane == 0) red[warp] = s;
    __syncthreads();
    float tot = 0.f;
    #pragma unroll
    for (int w = 0; w < 8; w++) tot += red[w];
    float inv = 1.f / tot;

    #pragma unroll
    for (int i = 0; i < 2; i++) {
        __half2 h0 = __floats2half2_rn(v[i].x * inv, v[i].y * inv);
        __half2 h1 = __floats2half2_rn(v[i].z * inv, v[i].w * inv);
        uint2 pk;
        pk.x = *reinterpret_cast<uint32_t*>(&h0);
        pk.y = *reinterpret_cast<uint32_t*>(&h1);
        *reinterpret_cast<uint2*>(ph + (tid + i * 256) * 4) = pk;
    }
}

// ---------------- mma.sync GEMM:  C[m][n] = sum_k A[m][k]*B[n][k]  (fp16) ----------------
// phase 0: A = Qh, B = Kh, out = g_scores, epilogue *= scale*sigmoid(span[n])
// phase 1: A = Ph, B = Vh, out = O
#define KC    64
#define NCH   (HID / KC)          // 32
#define ROWB  144                 // bytes per smem row (64 halves + 16 pad)
#define BUF   (128 * ROWB)        // 18432
#define STAGE (2 * BUF)           // 36864 : Ah, Bh
#define NSTG  3
#define SM_GATE (NSTG * STAGE)    // 110592
#define SM_TOT  (SM_GATE + 512)

__global__ __launch_bounds__(256, 2) void kgemm(int phase, const float* __restrict__ span,
                                                float* __restrict__ outp)
{
    extern __shared__ char smem[];
    const uint32_t su = smem_to_u32(smem);
    const int tid  = threadIdx.x;
    const int lane = tid & 31;
    const int wid  = tid >> 5;
    const int wm   = wid >> 2;       // 0..1, m offset = wm*64
    const int wn   = wid & 3;        // 0..3, n offset = wn*32
    const int b  = blockIdx.z;
    const int m0 = blockIdx.y * 128;
    const int n0 = blockIdx.x * 128;

    const __half* Ahp = (phase ? g_Ph : g_Qh) + (size_t)b * SEQ * HID + (size_t)m0 * HID;
    const __half* Bhp = (phase ? g_Vh : g_Kh) + (size_t)b * SEQ * HID + (size_t)n0 * HID;
    float* Cb = phase ? (outp + (size_t)b * SEQ * HID) : (g_scores + (size_t)b * SEQ * SEQ);

    float* gate_s = reinterpret_cast<float*>(smem + SM_GATE);
    if (tid < 128) {
        if (phase == 0) {
            const float scale = 0.02209708691207961f;   // 1/sqrt(2048)
            float sv = span[n0 + tid];
            gate_s[tid] = scale / (1.f + __expf(-sv));
        } else gate_s[tid] = 1.0f;
    }

    // 64 halves per row = 128 B: each thread copies 8 x 16B segments per stage
    auto load_stage = [&](int chunk, int s) {
        const int k0 = chunk * KC;
        uint32_t abase = su + (uint32_t)(s * STAGE);
        #pragma unroll
        for (int i = 0; i < 4; i++) {
            int idx = tid + i * 256;          // 0..1023
            int row = idx >> 3, seg = idx & 7;
            CP_ASYNC16(abase + row * ROWB + seg * 16,
                       Ahp + (size_t)row * HID + k0 + seg * 8);
        }
        uint32_t bbase = abase + BUF;
        #pragma unroll
        for (int i = 0; i < 4; i++) {
            int idx = tid + i * 256;
            int row = idx >> 3, seg = idx & 7;
            CP_ASYNC16(bbase + row * ROWB + seg * 16,
                       Bhp + (size_t)row * HID + k0 + seg * 8);
        }
        CP_COMMIT();
    };

    float acc[4][4][4];
    #pragma unroll
    for (int mi = 0; mi < 4; mi++)
        #pragma unroll
        for (int ni = 0; ni < 4; ni++)
            #pragma unroll
            for (int r = 0; r < 4; r++) acc[mi][ni][r] = 0.f;

    // double-buffered fragments (buffer index compile-time)
    uint32_t ahf[2][4][4], bhf[2][2][4];

    // ldmatrix lane-address components
    const int a_row  = wm * 64 + (lane & 15);                      // + mi*16
    const uint32_t a_koff = (uint32_t)((lane >> 4) * 16);
    const int b_row  = wn * 32 + ((lane >> 4) * 8) + (lane & 7);   // + p*16
    const uint32_t b_koff = (uint32_t)(((lane >> 3) & 1) * 16);

    #define LDSM_SLICE(stg, ks, bf) do {                                                \
        const uint32_t _base = su + (uint32_t)((stg) * STAGE);                          \
        const uint32_t _ko = (uint32_t)((ks) * 32);                                     \
        _Pragma("unroll")                                                               \
        for (int p = 0; p < 2; p++) {                                                   \
            uint32_t bd = _base + BUF + (uint32_t)((b_row + p * 16) * ROWB) + _ko + b_koff; \
            LDSM_X4(bhf[bf][p][0], bhf[bf][p][1], bhf[bf][p][2], bhf[bf][p][3], bd);    \
        }                                                                               \
        _Pragma("unroll")                                                               \
        for (int mi = 0; mi < 4; mi++) {                                                \
            uint32_t ad = _base + (uint32_t)((a_row + mi * 16) * ROWB) + _ko + a_koff;  \
            LDSM_X4(ahf[bf][mi][0], ahf[bf][mi][1], ahf[bf][mi][2], ahf[bf][mi][3], ad);\
        }                                                                               \
    } while (0)

    #define MMA_SLICE(bf) do {                                                          \
        _Pragma("unroll")                                                               \
        for (int mi = 0; mi < 4; mi++)                                                  \
            _Pragma("unroll")                                                           \
            for (int ni = 0; ni < 4; ni++)                                              \
                MMA16816(acc[mi][ni], ahf[bf][mi],                                      \
                         bhf[bf][ni >> 1][(ni & 1) * 2],                                \
                         bhf[bf][ni >> 1][(ni & 1) * 2 + 1]);                           \
    } while (0)

    // prologue: 2 stages in flight
    load_stage(0, 0);
    load_stage(1, 1);

    int s = 0;          // stage of chunk c
    for (int c = 0; c < NCH; c++) {
        // All issued loads complete -> chunks c AND c+1 resident (load(c+1) was
        // issued a full chunk ago, so this wait is ~free in steady state).
        CP_WAIT0();
        __syncthreads();                  // visibility + protect overwritten stage
        if (c + 2 < NCH) {
            int s2 = s + 2; if (s2 >= NSTG) s2 -= NSTG;
            load_stage(c + 2, s2);
        }

        if (c == 0) LDSM_SLICE(0, 0, 0);  // prime once; afterwards buf0 carries
                                          // slice 0 prefetched from the prior iter

        LDSM_SLICE(s, 1, 1);
        MMA_SLICE(0);
        LDSM_SLICE(s, 2, 0);
        MMA_SLICE(1);
        LDSM_SLICE(s, 3, 1);
        MMA_SLICE(0);
        if (c + 1 < NCH) {                // cross-chunk prefetch (c+1 resident ✓)
            int s1 = s + 1; if (s1 >= NSTG) s1 -= NSTG;
            LDSM_SLICE(s1, 0, 0);
        }
        MMA_SLICE(1);

        if (++s == NSTG) s = 0;
    }

    // epilogue
    #pragma unroll
    for (int mi = 0; mi < 4; mi++) {
        int r0 = m0 + wm * 64 + mi * 16 + (lane >> 2);
        #pragma unroll
        for (int ni = 0; ni < 4; ni++) {
            int cloc = wn * 32 + ni * 8 + (lane & 3) * 2;
            float g0 = gate_s[cloc], g1 = gate_s[cloc + 1];
            float2 v0 = make_float2(acc[mi][ni][0] * g0, acc[mi][ni][1] * g1);
            float2 v1 = make_float2(acc[mi][ni][2] * g0, acc[mi][ni][3] * g1);
            *reinterpret_cast<float2*>(&Cb[(size_t)r0 * 2048 + n0 + cloc]) = v0;
            *reinterpret_cast<float2*>(&Cb[(size_t)(r0 + 8) * 2048 + n0 + cloc]) = v1;
        }
    }
}

// -------------------------------------------------------------------------
extern "C" void kernel_launch(void* const* d_in, const int* in_sizes, int n_in,
                              void* d_out, int out_size)
{
    const float* Q    = (const float*)d_in[0];
    const float* K    = (const float*)d_in[1];
    const float* V    = (const float*)d_in[2];
    const float* span = (const float*)d_in[3];
    float* O = (float*)d_out;

    cudaFuncSetAttribute(kgemm, cudaFuncAttributeMaxDynamicSharedMemorySize, SM_TOT);

    const int n4 = (BATCH * SEQ * HID) / 4;          // float4 count
    kconv<<<n4 / 256, 256>>>((const float4*)Q, 0);
    kconv<<<n4 / 256, 256>>>((const float4*)K, 1);
    ktransV<<<dim3(HID / 32, SEQ / 32, BATCH), dim3(32, 8)>>>(V);

    dim3 gridG(SEQ / 128, SEQ / 128, BATCH);
    kgemm<<<gridG, 256, SM_TOT>>>(0, span, nullptr);
    ksoftmax<<<BATCH * SEQ, 256>>>();
    kgemm<<<gridG, 256, SM_TOT>>>(1, nullptr, O);
}